// round 2
// baseline (speedup 1.0000x reference)
#include <cuda_runtime.h>
#include <cstdint>

#define TM      64          // tokens per CTA
#define KS      1024        // codebook size
#define CDIM    256         // feature dim
#define CHUNK   64          // codes per SMEM chunk
#define NCHUNK  (KS / CHUNK)
#define HW      3136        // 56*56
#define NB      32          // batch
#define NTHREADS 256

__device__ __forceinline__ unsigned smem_u32(const void* p) {
    return (unsigned)__cvta_generic_to_shared(p);
}
__device__ __forceinline__ float ull_lo(unsigned long long v) {
    return __uint_as_float((unsigned)(v & 0xffffffffull));
}
__device__ __forceinline__ float ull_hi(unsigned long long v) {
    return __uint_as_float((unsigned)(v >> 32));
}

// Issue cp.async for one 64-code x 256-dim chunk into swizzled SMEM buffer.
// Swizzle: physical granule = logical_granule ^ (row & 7)   (granule = float4)
__device__ __forceinline__ void issue_chunk(const float* __restrict__ cb, int ch,
                                            float* buf, int tid) {
    const float* src = cb + (size_t)ch * CHUNK * CDIM;
    #pragma unroll
    for (int q = 0; q < 16; q++) {
        int f    = tid + NTHREADS * q;   // float4 id within chunk: 0..4095
        int code = f >> 6;               // 0..63
        int cg   = f & 63;               // logical granule within row
        int gp   = cg ^ (code & 7);      // swizzled granule
        unsigned daddr = smem_u32(buf + code * CDIM + gp * 4);
        const float4* g = (const float4*)(src + (size_t)code * CDIM) + cg;
        asm volatile("cp.async.cg.shared.global [%0], [%1], 16;\n"
                     :: "r"(daddr), "l"(g) : "memory");
    }
}

__global__ __launch_bounds__(NTHREADS, 1)
void vq_kernel(const float* __restrict__ x, const float* __restrict__ cb,
               const int* __restrict__ depth_ptr, float* __restrict__ out) {
    extern __shared__ float smem[];
    float* resid = smem;                         // [64][256] swizzled
    float* cbs0  = smem + TM * CDIM;             // chunk buffer 0
    float* cbs1  = smem + TM * CDIM + CHUNK * CDIM;

    const int tid = threadIdx.x;
    const int tx  = tid >> 4;      // 0..15  (token group; tokens tx+16i)
    const int ty  = tid & 15;      // 0..15  (code group; codes ty+16j in chunk)
    const int txs = tx & 7;
    const int tys = ty & 7;

    const int blk  = blockIdx.x;
    const int b    = blk / (HW / TM);
    const int tile = blk - b * (HW / TM);
    const int hw0  = tile * TM;
    const float* xb = x   + (size_t)b * CDIM * HW + hw0;
    float*       ob = out + (size_t)b * CDIM * HW + hw0;

    // ---- load resid tile: x is [B][C][H][W]; token = hw position ----
    {
        int lane = tid & 63;           // token within tile
        int grp  = tid >> 6;           // 0..3 -> 64 channels each
        #pragma unroll 8
        for (int cc = 0; cc < 64; cc++) {
            int c   = grp * 64 + cc;
            float v = xb[(size_t)c * HW + lane];
            int g   = (c >> 2) ^ (lane & 7);
            resid[lane * CDIM + g * 4 + (c & 3)] = v;
        }
    }
    __syncthreads();

    const int depth = depth_ptr ? *depth_ptr : 4;

    for (int step = 0; step < depth; step++) {
        float runv[4];
        int   runi[4];
        #pragma unroll
        for (int i = 0; i < 4; i++) { runv[i] = -3.0e38f; runi[i] = 0; }

        // prefetch chunk 0
        issue_chunk(cb, 0, cbs0, tid);
        asm volatile("cp.async.commit_group;\n" ::: "memory");

        for (int ch = 0; ch < NCHUNK; ch++) {
            float* buf = (ch & 1) ? cbs1 : cbs0;
            if (ch + 1 < NCHUNK) {
                issue_chunk(cb, ch + 1, ((ch + 1) & 1) ? cbs1 : cbs0, tid);
                asm volatile("cp.async.commit_group;\n" ::: "memory");
                asm volatile("cp.async.wait_group 1;\n" ::: "memory");
            } else {
                asm volatile("cp.async.wait_group 0;\n" ::: "memory");
            }
            __syncthreads();

            // ---- 64x64x256 fp32 GEMM micro-kernel (f32x2 packed FMA) ----
            unsigned long long aA[4][4], aB[4][4];
            #pragma unroll
            for (int i = 0; i < 4; i++)
                #pragma unroll
                for (int j = 0; j < 4; j++) { aA[i][j] = 0ull; aB[i][j] = 0ull; }

            for (int kg0 = 0; kg0 < 64; kg0 += 8) {
                #pragma unroll
                for (int u = 0; u < 8; u++) {
                    int gr = kg0 + (u ^ txs);   // physical granule for resid rows
                    int gc = kg0 + (u ^ tys);   // physical granule for cb rows
                    ulonglong2 rv[4], cv[4];
                    #pragma unroll
                    for (int i = 0; i < 4; i++)
                        rv[i] = *reinterpret_cast<const ulonglong2*>(
                                    resid + (tx + 16 * i) * CDIM + gr * 4);
                    #pragma unroll
                    for (int j = 0; j < 4; j++)
                        cv[j] = *reinterpret_cast<const ulonglong2*>(
                                    buf + (ty + 16 * j) * CDIM + gc * 4);
                    #pragma unroll
                    for (int i = 0; i < 4; i++) {
                        #pragma unroll
                        for (int j = 0; j < 4; j++) {
                            asm("fma.rn.f32x2 %0, %1, %2, %0;"
                                : "+l"(aA[i][j]) : "l"(rv[i].x), "l"(cv[j].x));
                            asm("fma.rn.f32x2 %0, %1, %2, %0;"
                                : "+l"(aB[i][j]) : "l"(rv[i].y), "l"(cv[j].y));
                        }
                    }
                }
            }

            // ---- per-token argmax over this chunk's 64 codes ----
            int cbase = ch * CHUNK;
            #pragma unroll
            for (int i = 0; i < 4; i++) {
                float bv = -3.0e38f;
                int   bi = 0x7fffffff;
                #pragma unroll
                for (int j = 0; j < 4; j++) {
                    float d = ull_lo(aA[i][j]) + ull_hi(aA[i][j])
                            + ull_lo(aB[i][j]) + ull_hi(aB[i][j]);
                    int cidx = cbase + ty + 16 * j;
                    if (d > bv) { bv = d; bi = cidx; }   // j ascending: ties keep first
                }
                // butterfly across the 16 ty-lanes (stays within half-warp)
                #pragma unroll
                for (int off = 8; off; off >>= 1) {
                    float ov = __shfl_xor_sync(0xffffffffu, bv, off);
                    int   oi = __shfl_xor_sync(0xffffffffu, bi, off);
                    if (ov > bv || (ov == bv && oi < bi)) { bv = ov; bi = oi; }
                }
                if (bv > runv[i] || (bv == runv[i] && bi < runi[i])) {
                    runv[i] = bv; runi[i] = bi;
                }
            }
            __syncthreads();   // compute on buf done before it is refilled
        }

        // ---- resid update: resid[tok] -= u * cb[code]  ----
        // Lanes ty of half-warp tx cooperatively update rows tx+16i (exclusive).
        #pragma unroll
        for (int i = 0; i < 4; i++) {
            int tok = tx + 16 * i;
            float u = runv[i];
            const float* crow = cb + (size_t)runi[i] * CDIM;
            #pragma unroll 4
            for (int cc = 0; cc < 16; cc++) {
                int c = cc * 16 + ty;
                int g = (c >> 2) ^ (tok & 7);
                resid[tok * CDIM + g * 4 + (c & 3)] -= u * crow[c];
            }
        }
        __syncthreads();
    }

    // ---- epilogue: out = x - final resid ----
    {
        int lane = tid & 63;
        int grp  = tid >> 6;
        #pragma unroll 8
        for (int cc = 0; cc < 64; cc++) {
            int c = grp * 64 + cc;
            int g = (c >> 2) ^ (lane & 7);
            float r = resid[lane * CDIM + g * 4 + (c & 3)];
            ob[(size_t)c * HW + lane] = xb[(size_t)c * HW + lane] - r;
        }
    }
}

extern "C" void kernel_launch(void* const* d_in, const int* in_sizes, int n_in,
                              void* d_out, int out_size) {
    const float* x  = (const float*)d_in[0];
    const float* cb = (const float*)d_in[1];
    const int* depth = (n_in > 2) ? (const int*)d_in[2] : nullptr;

    int smem_bytes = (TM * CDIM + 2 * CHUNK * CDIM) * (int)sizeof(float); // 192 KB
    cudaFuncSetAttribute(vq_kernel, cudaFuncAttributeMaxDynamicSharedMemorySize,
                         smem_bytes);

    dim3 grid(NB * (HW / TM));   // 32 * 49 = 1568 CTAs
    vq_kernel<<<grid, NTHREADS, smem_bytes>>>(x, cb, depth, (float*)d_out);
}

// round 7
// speedup vs baseline: 2.5903x; 2.5903x over previous
#include <cuda_runtime.h>
#include <cstdint>

#define HW    3136
#define CDIM  256
#define KS    1024
#define TM    32
#define ROWP  260          // resid row stride: float4-aligned, granule stride 65 (conflict-free)
#define NTHR  256
#define MAXC  32
#define EPS   0.02f

__device__ float g_G[KS * KS];
__device__ float g_cbT[CDIM * KS];

__device__ __forceinline__ unsigned long long pack2(float a, float b) {
    unsigned long long r;
    asm("mov.b64 %0, {%1, %2};" : "=l"(r) : "f"(a), "f"(b));
    return r;
}
__device__ __forceinline__ float u2lo(unsigned long long v) {
    return __uint_as_float((unsigned)(v & 0xffffffffull));
}
__device__ __forceinline__ float u2hi(unsigned long long v) {
    return __uint_as_float((unsigned)(v >> 32));
}

// R2-bit-exact decision dot: four interleaved sequential fmaf chains over
// ascending k (residue classes mod 4), combined ((s0+s1)+s2)+s3.
__device__ __forceinline__ float dot_r2(const float* __restrict__ r,
                                        const float* __restrict__ c) {
    float s0 = 0.f, s1 = 0.f, s2 = 0.f, s3 = 0.f;
    #pragma unroll 8
    for (int k4 = 0; k4 < 64; k4++) {
        float4 a = *reinterpret_cast<const float4*>(r + k4 * 4);
        float4 b = *reinterpret_cast<const float4*>(c + k4 * 4);
        s0 = fmaf(a.x, b.x, s0);
        s1 = fmaf(a.y, b.y, s1);
        s2 = fmaf(a.z, b.z, s2);
        s3 = fmaf(a.w, b.w, s3);
    }
    return ((s0 + s1) + s2) + s3;
}

// ---------------- cbT[k][c] = cb[c][k] ----------------
__global__ __launch_bounds__(256) void transpose_kernel(const float* __restrict__ cb) {
    int idx = blockIdx.x * 256 + threadIdx.x;
    int k = idx >> 10, c = idx & 1023;
    g_cbT[idx] = cb[(size_t)c * CDIM + k];
}

// ---------------- G = cb @ cb^T ----------------
__global__ __launch_bounds__(256) void gram_kernel(const float* __restrict__ cb) {
    __shared__ float a_s[32][65];
    __shared__ float b_s[32][65];
    int bi = blockIdx.x * 32, bj = blockIdx.y * 32;
    int r = threadIdx.x >> 5;
    int c = threadIdx.x & 31;
    float acc[4] = {0.f, 0.f, 0.f, 0.f};
    for (int kc = 0; kc < CDIM; kc += 64) {
        #pragma unroll
        for (int q = 0; q < 8; q++) {
            int idx = threadIdx.x + 256 * q;
            int rr = idx >> 6, kk = idx & 63;
            a_s[rr][kk] = cb[(size_t)(bi + rr) * CDIM + kc + kk];
            b_s[rr][kk] = cb[(size_t)(bj + rr) * CDIM + kc + kk];
        }
        __syncthreads();
        #pragma unroll 16
        for (int k = 0; k < 64; k++) {
            float bv = b_s[c][k];
            #pragma unroll
            for (int p = 0; p < 4; p++)
                acc[p] = fmaf(a_s[r + 8 * p][k], bv, acc[p]);
        }
        __syncthreads();
    }
    #pragma unroll
    for (int p = 0; p < 4; p++)
        g_G[(size_t)(bi + r + 8 * p) * KS + bj + c] = acc[p];
}

// ---------------- main fused kernel ----------------
__global__ __launch_bounds__(NTHR, 1)
void vq_main(const float* __restrict__ x, const float* __restrict__ cb,
             const int* __restrict__ depth_ptr, float* __restrict__ out)
{
    extern __shared__ float smf[];
    float* resid = smf;                          // [32][260]
    float* cbuf  = smf + TM * ROWP;              // [2][8][1024]
    float* redv  = cbuf + 2 * 8 * KS;            // [32][32]
    float* um    = redv + TM * 32;               // [32]
    int*   redi   = (int*)(um + TM);             // [32][8]
    int*   cm     = redi + TM * 8;               // [32]
    int*   ccount = cm + TM;                     // [32]
    int*   clist  = ccount + TM;                 // [32][MAXC]

    const int tid = threadIdx.x;
    const int tg = tid & 7;
    const int cg = tid >> 3;
    const int mx = (cg & 3) << 1;
    const int blk = blockIdx.x;
    const int b = blk / (HW / TM);
    const int tile = blk - b * (HW / TM);
    const int hw0 = tile * TM;
    const float* xb = x + (size_t)b * CDIM * HW + hw0;
    float* ob = out + (size_t)b * CDIM * HW + hw0;

    // ---- phase 1: load x tile (coalesced) ----
    {
        const int tok = tid & 31, ch0 = tid >> 5;
        #pragma unroll
        for (int it = 0; it < 32; it++) {
            int ch = it * 8 + ch0;
            resid[tok * ROWP + ch] = xb[(size_t)ch * HW + tok];
        }
    }
    __syncthreads();

    int depth = depth_ptr ? *depth_ptr : 4;
    if (depth > 16) depth = 16;
    if (depth < 0) depth = 0;

    // ---- phase 2: step-0 screen GEMM (smem-staged B, double-buffered) ----
    unsigned long long acc[4][16];
    #pragma unroll
    for (int i = 0; i < 4; i++)
        #pragma unroll
        for (int p = 0; p < 16; p++) acc[i][p] = 0ull;

    {
        float4 stg[8];
        #pragma unroll
        for (int r = 0; r < 8; r++) {
            int idx = tid + 256 * r;
            int row = idx >> 8, pos = idx & 255;
            stg[r] = *reinterpret_cast<const float4*>(g_cbT + (size_t)row * KS + pos * 4);
        }
        #pragma unroll
        for (int r = 0; r < 8; r++) {
            int idx = tid + 256 * r;
            int row = idx >> 8, pos = idx & 255;
            *reinterpret_cast<float4*>(cbuf + row * KS + pos * 4) = stg[r];
        }
        __syncthreads();

        #pragma unroll 1
        for (int s = 0; s < 32; s++) {
            if (s + 1 < 32) {
                #pragma unroll
                for (int r = 0; r < 8; r++) {
                    int idx = tid + 256 * r;
                    int row = idx >> 8, pos = idx & 255;
                    stg[r] = *reinterpret_cast<const float4*>(
                        g_cbT + (size_t)((s + 1) * 8 + row) * KS + pos * 4);
                }
            }
            const float* bb = cbuf + (s & 1) * (8 * KS);
            #pragma unroll
            for (int q = 0; q < 2; q++) {
                float4 av[4];
                #pragma unroll
                for (int i = 0; i < 4; i++)
                    av[i] = *reinterpret_cast<const float4*>(
                        resid + (tg + 8 * i) * ROWP + s * 8 + q * 4);
                #pragma unroll
                for (int kk = 0; kk < 4; kk++) {
                    const float* brow = bb + (q * 4 + kk) * KS + (cg << 5);
                    ulonglong2 bv[8];
                    #pragma unroll
                    for (int m = 0; m < 8; m++)
                        bv[m] = *reinterpret_cast<const ulonglong2*>(
                            brow + ((m ^ mx) << 2));
                    #pragma unroll
                    for (int i = 0; i < 4; i++) {
                        float a = (kk == 0) ? av[i].x : (kk == 1) ? av[i].y
                                : (kk == 2) ? av[i].z : av[i].w;
                        unsigned long long a2 = pack2(a, a);
                        #pragma unroll
                        for (int m = 0; m < 8; m++) {
                            asm("fma.rn.f32x2 %0, %1, %2, %0;"
                                : "+l"(acc[i][2 * m])     : "l"(a2), "l"(bv[m].x));
                            asm("fma.rn.f32x2 %0, %1, %2, %0;"
                                : "+l"(acc[i][2 * m + 1]) : "l"(a2), "l"(bv[m].y));
                        }
                    }
                }
            }
            if (s + 1 < 32) {
                __syncthreads();
                float* nb = cbuf + ((s + 1) & 1) * (8 * KS);
                #pragma unroll
                for (int r = 0; r < 8; r++) {
                    int idx = tid + 256 * r;
                    int row = idx >> 8, pos = idx & 255;
                    *reinterpret_cast<float4*>(nb + row * KS + pos * 4) = stg[r];
                }
                __syncthreads();
            }
        }
    }
    __syncthreads();

    // ---- per-step: screen max -> candidates -> R2-exact verify -> updates ----
    for (int t = 0; t < depth; t++) {
        if (tid < TM) ccount[tid] = 0;

        // thread-local screen max (value only)
        #pragma unroll
        for (int i = 0; i < 4; i++) {
            float bv = -3.0e38f;
            #pragma unroll
            for (int p = 0; p < 16; p++) {
                float lo = u2lo(acc[i][p]);
                float hi = u2hi(acc[i][p]);
                bv = fmaxf(bv, fmaxf(lo, hi));
            }
            redv[(tg + 8 * i) * 32 + cg] = bv;
        }
        __syncthreads();
        // cross-thread screen max
        {
            int tok = tid >> 3, j = tid & 7;
            float bv = redv[tok * 32 + j];
            #pragma unroll
            for (int jj = 8; jj < 32; jj += 8)
                bv = fmaxf(bv, redv[tok * 32 + j + jj]);
            #pragma unroll
            for (int d = 4; d; d >>= 1)
                bv = fmaxf(bv, __shfl_down_sync(0xffffffffu, bv, d, 8));
            if (j == 0) um[tok] = bv;
        }
        __syncthreads();

        // candidate collection: screened ip >= screen_max - EPS
        #pragma unroll
        for (int i = 0; i < 4; i++) {
            int tok = tg + 8 * i;
            float thr = um[tok] - EPS;
            #pragma unroll
            for (int p = 0; p < 16; p++) {
                float lo = u2lo(acc[i][p]);
                float hi = u2hi(acc[i][p]);
                int c0 = (cg << 5) + ((((p >> 1) ^ mx)) << 2) + ((p & 1) << 1);
                if (lo >= thr) {
                    int s = atomicAdd(&ccount[tok], 1);
                    if (s < MAXC) clist[tok * MAXC + s] = c0;
                }
                if (hi >= thr) {
                    int s = atomicAdd(&ccount[tok], 1);
                    if (s < MAXC) clist[tok * MAXC + s] = c0 + 1;
                }
            }
        }
        __syncthreads();

        // R2-bit-exact verify: 8 threads per token, each computes full scalar
        // dots (R2 summation order) for its strided share of candidates.
        {
            int tok = tid >> 3, j = tid & 7;
            int raw = ccount[tok];
            const float* rr = resid + tok * ROWP;
            float bv = -3.0e38f; int bi = 0x7fffffff;
            if (raw > 0 && raw <= MAXC) {
                for (int q = j; q < raw; q += 8) {
                    int c = clist[tok * MAXC + q];
                    float s = dot_r2(rr, cb + (size_t)c * CDIM);
                    if (s > bv || (s == bv && c < bi)) { bv = s; bi = c; }
                }
            } else {
                // fallback: exact scan over ALL codes (same arithmetic)
                for (int c = j; c < KS; c += 8) {
                    float s = dot_r2(rr, cb + (size_t)c * CDIM);
                    if (s > bv || (s == bv && c < bi)) { bv = s; bi = c; }
                }
            }
            redv[tok * 32 + j] = bv;
            redi[tok * 8 + j] = bi;
            __syncwarp();
            #pragma unroll
            for (int d = 4; d; d >>= 1) {
                float ov = __shfl_down_sync(0xffffffffu, bv, d, 8);
                int   oi = __shfl_down_sync(0xffffffffu, bi, d, 8);
                if (ov > bv || (ov == bv && oi < bi)) { bv = ov; bi = oi; }
            }
            if (j == 0) { um[tok] = bv; cm[tok] = bi; }
        }
        __syncthreads();

        // exact resid update (same fused expression as R2)
        {
            int tok = tid >> 3, part = tid & 7;
            float u = um[tok];
            const float* crow = cb + (size_t)cm[tok] * CDIM;
            #pragma unroll 8
            for (int cc = 0; cc < 32; cc++) {
                int ch = cc * 8 + part;
                resid[tok * ROWP + ch] -= u * crow[ch];
            }
        }
        // Gram screen update: ip -= u * G[c]
        if (t + 1 < depth) {
            #pragma unroll
            for (int i = 0; i < 4; i++) {
                int tok = tg + 8 * i;
                float u = um[tok]; int c = cm[tok];
                const float* Gr = g_G + (size_t)c * KS + (cg << 5);
                unsigned long long nu = pack2(-u, -u);
                #pragma unroll
                for (int m = 0; m < 8; m++) {
                    ulonglong2 g = *reinterpret_cast<const ulonglong2*>(
                        Gr + ((m ^ mx) << 2));
                    asm("fma.rn.f32x2 %0, %1, %2, %0;"
                        : "+l"(acc[i][2 * m])     : "l"(nu), "l"(g.x));
                    asm("fma.rn.f32x2 %0, %1, %2, %0;"
                        : "+l"(acc[i][2 * m + 1]) : "l"(nu), "l"(g.y));
                }
            }
        }
        __syncthreads();
    }

    // ---- epilogue: out = x - resid_final (coalesced) ----
    {
        const int tok = tid & 31, ch0 = tid >> 5;
        #pragma unroll
        for (int it = 0; it < 32; it++) {
            int ch = it * 8 + ch0;
            ob[(size_t)ch * HW + tok] = xb[(size_t)ch * HW + tok] - resid[tok * ROWP + ch];
        }
    }
}

extern "C" void kernel_launch(void* const* d_in, const int* in_sizes, int n_in,
                              void* d_out, int out_size) {
    const float* x  = (const float*)d_in[0];
    const float* cb = (const float*)d_in[1];
    const int* depth = (n_in > 2) ? (const int*)d_in[2] : nullptr;

    int B = in_sizes[0] / (CDIM * HW);   // 32

    transpose_kernel<<<1024, 256>>>(cb);
    gram_kernel<<<dim3(32, 32), 256>>>(cb);

    int smem_bytes = (TM * ROWP + 2 * 8 * KS + TM * 32 + TM) * (int)sizeof(float)
                   + (TM * 8 + TM + TM + TM * MAXC) * (int)sizeof(int);
    cudaFuncSetAttribute(vq_main, cudaFuncAttributeMaxDynamicSharedMemorySize, smem_bytes);
    vq_main<<<B * (HW / TM), NTHR, smem_bytes>>>(x, cb, depth, (float*)d_out);
}

// round 8
// speedup vs baseline: 4.4509x; 1.7183x over previous
#include <cuda_runtime.h>
#include <cstdint>

#define HW    3136
#define CDIM  256
#define KS    1024
#define TM    32
#define ROWP  260          // resid row stride (floats), 16B-aligned rows
#define IPS   1036         // ip row stride (floats), 16B-aligned, bank-staggered
#define NTHR  256
#define MAXC  64
#define EPS   0.05f

__device__ float g_G[KS * KS];
__device__ uint2 g_cbB[16 * KS * 4];   // [kchunk][code][tp] pre-swizzled bf16 fragments

__device__ __forceinline__ unsigned pbf(float hi, float lo) {
    unsigned r;
    asm("cvt.rn.bf16x2.f32 %0, %1, %2;" : "=r"(r) : "f"(hi), "f"(lo));
    return r;
}

// R2-bit-exact decision dot: four interleaved sequential fmaf chains over
// ascending k (residue classes mod 4), combined ((s0+s1)+s2)+s3.
__device__ __forceinline__ float dot_r2(const float* __restrict__ r,
                                        const float* __restrict__ c) {
    float s0 = 0.f, s1 = 0.f, s2 = 0.f, s3 = 0.f;
    #pragma unroll 8
    for (int k4 = 0; k4 < 64; k4++) {
        float4 a = *reinterpret_cast<const float4*>(r + k4 * 4);
        float4 b = *reinterpret_cast<const float4*>(c + k4 * 4);
        s0 = fmaf(a.x, b.x, s0);
        s1 = fmaf(a.y, b.y, s1);
        s2 = fmaf(a.z, b.z, s2);
        s3 = fmaf(a.w, b.w, s3);
    }
    return ((s0 + s1) + s2) + s3;
}

// ---------------- B fragment packing: bf16 codebook, mma-ready ----------------
// element (kc, code, tp): .x = {lo: cb[code][16kc+2tp], hi: [..+1]}
//                         .y = {lo: cb[code][16kc+2tp+8], hi: [..+9]}
__global__ __launch_bounds__(256) void pack_b_kernel(const float* __restrict__ cb) {
    int idx = blockIdx.x * 256 + threadIdx.x;      // 65536 total
    int kc = idx >> 12, code = (idx >> 2) & 1023, tp = idx & 3;
    const float* row = cb + (size_t)code * CDIM + kc * 16;
    uint2 v;
    v.x = pbf(row[2 * tp + 1], row[2 * tp]);
    v.y = pbf(row[2 * tp + 9], row[2 * tp + 8]);
    g_cbB[idx] = v;
}

// ---------------- G = cb @ cb^T ----------------
__global__ __launch_bounds__(256) void gram_kernel(const float* __restrict__ cb) {
    __shared__ float a_s[32][65];
    __shared__ float b_s[32][65];
    int bi = blockIdx.x * 32, bj = blockIdx.y * 32;
    int r = threadIdx.x >> 5;
    int c = threadIdx.x & 31;
    float acc[4] = {0.f, 0.f, 0.f, 0.f};
    for (int kc = 0; kc < CDIM; kc += 64) {
        #pragma unroll
        for (int q = 0; q < 8; q++) {
            int idx = threadIdx.x + 256 * q;
            int rr = idx >> 6, kk = idx & 63;
            a_s[rr][kk] = cb[(size_t)(bi + rr) * CDIM + kc + kk];
            b_s[rr][kk] = cb[(size_t)(bj + rr) * CDIM + kc + kk];
        }
        __syncthreads();
        #pragma unroll 16
        for (int k = 0; k < 64; k++) {
            float bv = b_s[c][k];
            #pragma unroll
            for (int p = 0; p < 4; p++)
                acc[p] = fmaf(a_s[r + 8 * p][k], bv, acc[p]);
        }
        __syncthreads();
    }
    #pragma unroll
    for (int p = 0; p < 4; p++)
        g_G[(size_t)(bi + r + 8 * p) * KS + bj + c] = acc[p];
}

// ---------------- main fused kernel ----------------
__global__ __launch_bounds__(NTHR, 1)
void vq_main(const float* __restrict__ x, const float* __restrict__ cb,
             const int* __restrict__ depth_ptr, float* __restrict__ out)
{
    extern __shared__ float smf[];
    float* resid = smf;                          // [32][260]
    float* ip    = smf + TM * ROWP;              // [32][1036] fp32 screened ip
    float* redv  = ip + TM * IPS;                // [32][32]
    float* um    = redv + TM * 32;               // [32]
    int*   cm     = (int*)(um + TM);             // [32]
    int*   ccount = cm + TM;                     // [32]
    int*   clist  = ccount + TM;                 // [32][MAXC]

    const int tid = threadIdx.x;
    const int tg = tid & 7;
    const int cg = tid >> 3;
    const int blk = blockIdx.x;
    const int b = blk / (HW / TM);
    const int tile = blk - b * (HW / TM);
    const int hw0 = tile * TM;
    const float* xb = x + (size_t)b * CDIM * HW + hw0;
    float* ob = out + (size_t)b * CDIM * HW + hw0;

    // ---- phase 1: load x tile (coalesced) ----
    {
        const int tok = tid & 31, ch0 = tid >> 5;
        #pragma unroll
        for (int it = 0; it < 32; it++) {
            int ch = it * 8 + ch0;
            resid[tok * ROWP + ch] = xb[(size_t)ch * HW + tok];
        }
    }
    __syncthreads();

    int depth = depth_ptr ? *depth_ptr : 4;
    if (depth > 16) depth = 16;
    if (depth < 0) depth = 0;

    // ---- phase 2: bf16 tensor-core screen GEMM -> ip (fp32 in smem) ----
    // Warp w computes D[32 tokens][codes 128w..128w+128). mma.m16n8k16:
    // lane: g = lane>>2 (row/col group), tp = lane&3 (k pair index).
    {
        const int w = tid >> 5, lane = tid & 31;
        const int g = lane >> 2, tp = lane & 3;
        const int codebase = w * 128;
        float acc[16][8];
        #pragma unroll
        for (int n = 0; n < 16; n++)
            #pragma unroll
            for (int q = 0; q < 8; q++) acc[n][q] = 0.f;

        const uint2* Bbase = g_cbB + (size_t)(codebase + g) * 4 + tp;
        uint2 bb[2][16];
        #pragma unroll
        for (int n = 0; n < 16; n++) bb[0][n] = __ldg(Bbase + n * 32);

        #pragma unroll
        for (int kc = 0; kc < 16; kc++) {
            const int cur = kc & 1;
            if (kc < 15) {
                #pragma unroll
                for (int n = 0; n < 16; n++)
                    bb[cur ^ 1][n] = __ldg(Bbase + (size_t)(kc + 1) * 4096 + n * 32);
            }
            const int k0 = kc * 16 + 2 * tp;
            unsigned a[2][4];
            #pragma unroll
            for (int m = 0; m < 2; m++) {
                const float* r0 = resid + (m * 16 + g) * ROWP + k0;
                const float* r1 = resid + (m * 16 + g + 8) * ROWP + k0;
                float2 p0 = *reinterpret_cast<const float2*>(r0);
                float2 p1 = *reinterpret_cast<const float2*>(r1);
                float2 p2 = *reinterpret_cast<const float2*>(r0 + 8);
                float2 p3 = *reinterpret_cast<const float2*>(r1 + 8);
                a[m][0] = pbf(p0.y, p0.x);
                a[m][1] = pbf(p1.y, p1.x);
                a[m][2] = pbf(p2.y, p2.x);
                a[m][3] = pbf(p3.y, p3.x);
            }
            #pragma unroll
            for (int n = 0; n < 16; n++) {
                #pragma unroll
                for (int m = 0; m < 2; m++) {
                    asm("mma.sync.aligned.m16n8k16.row.col.f32.bf16.bf16.f32 "
                        "{%0,%1,%2,%3}, {%4,%5,%6,%7}, {%8,%9}, {%0,%1,%2,%3};"
                        : "+f"(acc[n][m * 4 + 0]), "+f"(acc[n][m * 4 + 1]),
                          "+f"(acc[n][m * 4 + 2]), "+f"(acc[n][m * 4 + 3])
                        : "r"(a[m][0]), "r"(a[m][1]), "r"(a[m][2]), "r"(a[m][3]),
                          "r"(bb[cur][n].x), "r"(bb[cur][n].y));
                }
            }
        }
        // write D -> ip smem (c0,c1 row g; c2,c3 row g+8)
        #pragma unroll
        for (int n = 0; n < 16; n++) {
            int col = codebase + n * 8 + 2 * tp;
            #pragma unroll
            for (int m = 0; m < 2; m++) {
                int r0 = m * 16 + g;
                *reinterpret_cast<float2*>(ip + r0 * IPS + col) =
                    make_float2(acc[n][m * 4 + 0], acc[n][m * 4 + 1]);
                *reinterpret_cast<float2*>(ip + (r0 + 8) * IPS + col) =
                    make_float2(acc[n][m * 4 + 2], acc[n][m * 4 + 3]);
            }
        }
    }
    __syncthreads();

    // ---- per-step: screen max -> candidates -> R2-exact verify -> updates ----
    for (int t = 0; t < depth; t++) {
        if (tid < TM) ccount[tid] = 0;

        // thread-local screen max over smem ip (thread: 4 tokens x 32 codes)
        #pragma unroll
        for (int i = 0; i < 4; i++) {
            int tok = tg + 8 * i;
            const float4* p = reinterpret_cast<const float4*>(ip + tok * IPS + (cg << 5));
            float bv = -3.0e38f;
            #pragma unroll
            for (int j = 0; j < 8; j++) {
                float4 v = p[j];
                bv = fmaxf(bv, fmaxf(fmaxf(v.x, v.y), fmaxf(v.z, v.w)));
            }
            redv[tok * 32 + cg] = bv;
        }
        __syncthreads();
        // cross-thread screen max
        {
            int tok = tid >> 3, j = tid & 7;
            float bv = redv[tok * 32 + j];
            #pragma unroll
            for (int jj = 8; jj < 32; jj += 8)
                bv = fmaxf(bv, redv[tok * 32 + j + jj]);
            #pragma unroll
            for (int d = 4; d; d >>= 1)
                bv = fmaxf(bv, __shfl_down_sync(0xffffffffu, bv, d, 8));
            if (j == 0) um[tok] = bv;
        }
        __syncthreads();

        // candidate collection: screened ip >= screen_max - EPS
        #pragma unroll
        for (int i = 0; i < 4; i++) {
            int tok = tg + 8 * i;
            float thr = um[tok] - EPS;
            const float4* p = reinterpret_cast<const float4*>(ip + tok * IPS + (cg << 5));
            #pragma unroll
            for (int j = 0; j < 8; j++) {
                float4 v = p[j];
                int c0 = (cg << 5) + 4 * j;
                if (v.x >= thr) { int s = atomicAdd(&ccount[tok], 1); if (s < MAXC) clist[tok * MAXC + s] = c0; }
                if (v.y >= thr) { int s = atomicAdd(&ccount[tok], 1); if (s < MAXC) clist[tok * MAXC + s] = c0 + 1; }
                if (v.z >= thr) { int s = atomicAdd(&ccount[tok], 1); if (s < MAXC) clist[tok * MAXC + s] = c0 + 2; }
                if (v.w >= thr) { int s = atomicAdd(&ccount[tok], 1); if (s < MAXC) clist[tok * MAXC + s] = c0 + 3; }
            }
        }
        __syncthreads();

        // R2-bit-exact verify: 8 threads per token, strided candidates
        {
            int tok = tid >> 3, j = tid & 7;
            int raw = ccount[tok];
            const float* rr = resid + tok * ROWP;
            float bv = -3.0e38f; int bi = 0x7fffffff;
            if (raw > 0 && raw <= MAXC) {
                for (int q = j; q < raw; q += 8) {
                    int c = clist[tok * MAXC + q];
                    float s = dot_r2(rr, cb + (size_t)c * CDIM);
                    if (s > bv || (s == bv && c < bi)) { bv = s; bi = c; }
                }
            } else {
                // fallback: exact scan over ALL codes (same arithmetic)
                for (int c = j; c < KS; c += 8) {
                    float s = dot_r2(rr, cb + (size_t)c * CDIM);
                    if (s > bv || (s == bv && c < bi)) { bv = s; bi = c; }
                }
            }
            #pragma unroll
            for (int d = 4; d; d >>= 1) {
                float ov = __shfl_down_sync(0xffffffffu, bv, d, 8);
                int   oi = __shfl_down_sync(0xffffffffu, bi, d, 8);
                if (ov > bv || (ov == bv && oi < bi)) { bv = ov; bi = oi; }
            }
            if (j == 0) { um[tok] = bv; cm[tok] = bi; }
        }
        __syncthreads();

        // exact resid update (same fused expression as R2)
        {
            int tok = tid >> 3, part = tid & 7;
            float u = um[tok];
            const float* crow = cb + (size_t)cm[tok] * CDIM;
            #pragma unroll 8
            for (int cc = 0; cc < 32; cc++) {
                int ch = cc * 8 + part;
                resid[tok * ROWP + ch] -= u * crow[ch];
            }
        }
        // Gram screen update in smem: ip[tok][c'] -= u * G[c][c']
        if (t + 1 < depth) {
            #pragma unroll
            for (int i = 0; i < 4; i++) {
                int tok = tg + 8 * i;
                float u = um[tok]; int c = cm[tok];
                const float4* Gr = reinterpret_cast<const float4*>(
                    g_G + (size_t)c * KS + (cg << 5));
                float4* pp = reinterpret_cast<float4*>(ip + tok * IPS + (cg << 5));
                #pragma unroll
                for (int m = 0; m < 8; m++) {
                    float4 g4 = Gr[m];
                    float4 v = pp[m];
                    v.x -= u * g4.x; v.y -= u * g4.y;
                    v.z -= u * g4.z; v.w -= u * g4.w;
                    pp[m] = v;
                }
            }
        }
        __syncthreads();
    }

    // ---- epilogue: out = x - resid_final (coalesced) ----
    {
        const int tok = tid & 31, ch0 = tid >> 5;
        #pragma unroll
        for (int it = 0; it < 32; it++) {
            int ch = it * 8 + ch0;
            ob[(size_t)ch * HW + tok] = xb[(size_t)ch * HW + tok] - resid[tok * ROWP + ch];
        }
    }
}

extern "C" void kernel_launch(void* const* d_in, const int* in_sizes, int n_in,
                              void* d_out, int out_size) {
    const float* x  = (const float*)d_in[0];
    const float* cb = (const float*)d_in[1];
    const int* depth = (n_in > 2) ? (const int*)d_in[2] : nullptr;

    int B = in_sizes[0] / (CDIM * HW);   // 32

    pack_b_kernel<<<256, 256>>>(cb);
    gram_kernel<<<dim3(32, 32), 256>>>(cb);

    int smem_bytes = (TM * ROWP + TM * IPS + TM * 32 + TM) * (int)sizeof(float)
                   + (TM + TM + TM * MAXC) * (int)sizeof(int);
    cudaFuncSetAttribute(vq_main, cudaFuncAttributeMaxDynamicSharedMemorySize, smem_bytes);
    vq_main<<<B * (HW / TM), NTHR, smem_bytes>>>(x, cb, depth, (float*)d_out);
}